// round 1
// baseline (speedup 1.0000x reference)
#include <cuda_runtime.h>

#define NTOT 131072
#define BATCH 32

typedef unsigned long long ull;

// ---------- f32x2 packed-math helpers (sm_103a) ----------
__device__ __forceinline__ ull f2pack(float lo, float hi) {
    ull r; asm("mov.b64 %0, {%1, %2};" : "=l"(r) : "f"(lo), "f"(hi)); return r;
}
__device__ __forceinline__ void f2unpack(float& lo, float& hi, ull v) {
    asm("mov.b64 {%0, %1}, %2;" : "=f"(lo), "=f"(hi) : "l"(v));
}
__device__ __forceinline__ ull ffma2(ull a, ull b, ull c) {
    ull d; asm("fma.rn.f32x2 %0, %1, %2, %3;" : "=l"(d) : "l"(a), "l"(b), "l"(c)); return d;
}

// ---------- scratch (device globals; no allocation) ----------
__device__ float g_xT[NTOT * BATCH];      // x transposed: [i][n], 16 MB
__device__ float g_yT[NTOT * BATCH];      // y accumulator: [i][n], 16 MB
__device__ float g_t[8515584];            // per-level t buffers: [block][r][n]

// ---------- transposes ----------
__global__ void k_transpose_in(const float* __restrict__ x) {
    __shared__ float tile[32][33];
    int i0 = blockIdx.x * 32;
    int tx = threadIdx.x, ty = threadIdx.y;
    tile[ty][tx] = x[(size_t)ty * NTOT + i0 + tx];   // ty = batch n, tx = i
    __syncthreads();
    g_xT[(size_t)(i0 + ty) * BATCH + tx] = tile[tx][ty];
}

__global__ void k_transpose_out(float* __restrict__ out) {
    __shared__ float tile[32][33];
    int i0 = blockIdx.x * 32;
    int tx = threadIdx.x, ty = threadIdx.y;
    tile[ty][tx] = g_yT[(size_t)(i0 + ty) * BATCH + tx];  // ty = i, tx = n
    __syncthreads();
    out[(size_t)ty * NTOT + i0 + tx] = tile[tx][ty];
}

__global__ void k_zero_t(int count) {
    int i = blockIdx.x * blockDim.x + threadIdx.x;
    if (i < count) g_t[i] = 0.f;
}

// ---------- leaf: y[k,t,:] = lb[k,t,:] @ x[k,:,:] ----------
__global__ void k_leaf(const float* __restrict__ lb) {
    int k = blockIdx.x;                 // 4096 leaf blocks
    __shared__ float xs[32][32];        // [s][n]
    __shared__ float a[32][33];         // [t][s]
    int tid = threadIdx.x;
    for (int idx = tid; idx < 1024; idx += 256) {
        xs[idx >> 5][idx & 31] = g_xT[k * 1024 + idx];
        a[idx >> 5][idx & 31]  = lb[k * 1024 + idx];
    }
    __syncthreads();
    int n = tid & 31;
    for (int t = tid >> 5; t < 32; t += 8) {
        float acc = 0.f;
        #pragma unroll
        for (int s = 0; s < 32; s++) acc += a[t][s] * xs[s][n];
        g_yT[(size_t)(k * 32 + t) * BATCH + n] = acc;
    }
}

// ---------- phase 1: t[block, r, n] = sum_s U[block, s, r] * x[n, block, s] ----------
template<int R, int RW, bool STORE>
__device__ __forceinline__ void p1_work(const float* __restrict__ u, int ibase,
                                        int sdim, int block, int r0, int toff, int lane) {
    ull a0 = 0, a1 = 0, a2 = 0, a3 = 0;
    const char* up = (const char*)u + ((size_t)ibase * R + r0) * 4;
    const float* xp = g_xT + (size_t)ibase * BATCH + lane;
    #pragma unroll 4
    for (int sl = 0; sl < sdim; sl++) {
        float xv = __ldg(xp); xp += BATCH;
        ull x2 = f2pack(xv, xv);
        ulonglong2 uv = __ldg((const ulonglong2*)up);            // u[r0..r0+3]
        a0 = ffma2(uv.x, x2, a0);
        a1 = ffma2(uv.y, x2, a1);
        if (RW == 8) {
            ulonglong2 uv2 = __ldg((const ulonglong2*)(up + 16)); // u[r0+4..r0+7]
            a2 = ffma2(uv2.x, x2, a2);
            a3 = ffma2(uv2.y, x2, a3);
        }
        up += (size_t)R * 4;
    }
    float* td = g_t + toff + ((size_t)block * R + r0) * BATCH + lane;
    float lo, hi;
    f2unpack(lo, hi, a0);
    if (STORE) { td[0]  = lo; td[32] = hi; } else { atomicAdd(td,      lo); atomicAdd(td + 32,  hi); }
    f2unpack(lo, hi, a1);
    if (STORE) { td[64] = lo; td[96] = hi; } else { atomicAdd(td + 64, lo); atomicAdd(td + 96,  hi); }
    if (RW == 8) {
        f2unpack(lo, hi, a2);
        if (STORE) { td[128] = lo; td[160] = hi; } else { atomicAdd(td + 128, lo); atomicAdd(td + 160, hi); }
        f2unpack(lo, hi, a3);
        if (STORE) { td[192] = lo; td[224] = hi; } else { atomicAdd(td + 192, lo); atomicAdd(td + 224, hi); }
    }
}

template<int R, bool STORE>
__global__ void __launch_bounds__(256) k_phase1(const float* __restrict__ u, int bsz, int toff) {
    constexpr int FULL = R / 8;
    constexpr int HASTAIL = (R % 8) ? 1 : 0;
    constexpr int NTILE = FULL + HASTAIL;
    int w = threadIdx.x >> 5, lane = threadIdx.x & 31;
    int s0 = blockIdx.x * 256;
    int sdim = bsz < 256 ? bsz : 256;
    int nbw = 256 / sdim;
    int items = nbw * NTILE;
    for (int item = w; item < items; item += 8) {
        int bw = item / NTILE;
        int tile = item - bw * NTILE;
        int ibase = s0 + bw * sdim;
        int block = ibase / bsz;
        if (HASTAIL && tile == FULL)
            p1_work<R, 4, STORE>(u, ibase, sdim, block, FULL * 8, toff, lane);
        else
            p1_work<R, 8, STORE>(u, ibase, sdim, block, tile * 8, toff, lane);
    }
}

// ---------- phase 2: y[n, block, s] += s2 * sum_r U[block, s, r] * t[sibling, r, n] ----------
template<int R>
__global__ void __launch_bounds__(256) k_phase2(const float* __restrict__ u, int bsz, int toff,
                                                const float* __restrict__ scale) {
    int w = threadIdx.x >> 5, lane = threadIdx.x & 31;
    int gs0 = blockIdx.x * 256 + w * 32;      // warp's 32 consecutive s (within one block: bsz >= 32)
    int block = gs0 / bsz;
    int sib = block ^ 1;
    const float* tb = g_t + toff + (size_t)sib * (R * BATCH);
    ull tp[R / 2];
    #pragma unroll
    for (int j = 0; j < R / 2; j++) {
        float t0 = __ldg(tb + (2 * j) * BATCH + lane);
        float t1 = __ldg(tb + (2 * j + 1) * BATCH + lane);
        tp[j] = f2pack(t0, t1);
    }
    float sc = __ldg(scale);
    float s2 = sc * sc;
    const char* up = (const char*)u + (size_t)gs0 * R * 4;
    float* yp = g_yT + (size_t)gs0 * BATCH + lane;
    for (int sl = 0; sl < 32; sl++) {
        ull a0 = 0, a1 = 0, a2 = 0, a3 = 0;
        #pragma unroll
        for (int j = 0; j < R / 4; j++) {
            ulonglong2 uv = __ldg((const ulonglong2*)(up + j * 16));   // u[4j..4j+3]
            if (j & 1) { a2 = ffma2(uv.x, tp[2 * j], a2); a3 = ffma2(uv.y, tp[2 * j + 1], a3); }
            else       { a0 = ffma2(uv.x, tp[2 * j], a0); a1 = ffma2(uv.y, tp[2 * j + 1], a1); }
        }
        float l0, h0, l1, h1, l2, h2, l3, h3;
        f2unpack(l0, h0, a0); f2unpack(l1, h1, a1);
        f2unpack(l2, h2, a2); f2unpack(l3, h3, a3);
        float v = ((l0 + h0) + (l1 + h1)) + ((l2 + h2) + (l3 + h3));
        *yp += s2 * v;
        yp += BATCH;
        up += (size_t)R * 4;
    }
}

// ---------- driver ----------
extern "C" void kernel_launch(void* const* d_in, const int* in_sizes, int n_in,
                              void* d_out, int out_size) {
    (void)in_sizes; (void)n_in; (void)out_size;
    const float* x  = (const float*)d_in[0];
    const float* lb = (const float*)d_in[1];
    const float* sc = (const float*)d_in[2];
    const float* u[12];
    for (int l = 0; l < 12; l++) u[l] = (const float*)d_in[3 + l];
    float* out = (float*)d_out;

    static const int RK[12] = {64, 64, 64, 64, 64, 64, 64, 64, 64, 52, 32, 20};
    int toff[12]; int acc = 0;
    for (int l = 0; l < 12; l++) {
        toff[l] = acc;
        int bsz = 32 << (11 - l);
        acc += (NTOT / bsz) * RK[l] * 32;
    }
    int zero_count = toff[8];   // only atomic levels (0-7) need pre-zeroed t

    k_transpose_in<<<4096, dim3(32, 32)>>>(x);
    k_zero_t<<<(zero_count + 1023) / 1024, 1024>>>(zero_count);
    k_leaf<<<4096, 256>>>(lb);

    for (int l = 0; l < 12; l++) {
        int bsz = 32 << (11 - l);
        switch (RK[l]) {
            case 64:
                if (bsz > 256) k_phase1<64, false><<<512, 256>>>(u[l], bsz, toff[l]);
                else           k_phase1<64, true ><<<512, 256>>>(u[l], bsz, toff[l]);
                break;
            case 52: k_phase1<52, true><<<512, 256>>>(u[l], bsz, toff[l]); break;
            case 32: k_phase1<32, true><<<512, 256>>>(u[l], bsz, toff[l]); break;
            case 20: k_phase1<20, true><<<512, 256>>>(u[l], bsz, toff[l]); break;
        }
    }
    for (int l = 0; l < 12; l++) {
        int bsz = 32 << (11 - l);
        switch (RK[l]) {
            case 64: k_phase2<64><<<512, 256>>>(u[l], bsz, toff[l], sc); break;
            case 52: k_phase2<52><<<512, 256>>>(u[l], bsz, toff[l], sc); break;
            case 32: k_phase2<32><<<512, 256>>>(u[l], bsz, toff[l], sc); break;
            case 20: k_phase2<20><<<512, 256>>>(u[l], bsz, toff[l], sc); break;
        }
    }
    k_transpose_out<<<4096, dim3(32, 32)>>>(out);
}

// round 2
// speedup vs baseline: 1.2579x; 1.2579x over previous
#include <cuda_runtime.h>

#define NTOT 131072
#define BATCH 32

typedef unsigned long long ull;

// ---------- f32x2 packed-math helpers (sm_103a) ----------
__device__ __forceinline__ ull f2pack(float lo, float hi) {
    ull r; asm("mov.b64 %0, {%1, %2};" : "=l"(r) : "f"(lo), "f"(hi)); return r;
}
__device__ __forceinline__ void f2unpack(float& lo, float& hi, ull v) {
    asm("mov.b64 {%0, %1}, %2;" : "=f"(lo), "=f"(hi) : "l"(v));
}
__device__ __forceinline__ ull ffma2(ull a, ull b, ull c) {
    ull d; asm("fma.rn.f32x2 %0, %1, %2, %3;" : "=l"(d) : "l"(a), "l"(b), "l"(c)); return d;
}

// ---------- scratch (device globals; no allocation) ----------
__device__ float g_xT[NTOT * BATCH];   // x transposed: [i][n], 16 MB
__device__ float g_t[8515584];         // per-level t buffers: [block][r][n]

// level tables (R: 9x64, 52, 32, 20; bsz = 32<<(11-l))
__device__ __constant__ const int c_dummy = 0; // (unused, keeps nvcc happy)

struct P { const float* u[12]; };

// t-buffer offsets per level (floats)
#define TOFF0 0
#define TOFF1 4096
#define TOFF2 12288
#define TOFF3 28672
#define TOFF4 61440
#define TOFF5 126976
#define TOFF6 258048
#define TOFF7 520192
#define TOFF8 1044480
#define TOFF9 2093056
#define TOFF10 3796992
#define TOFF11 5894144
#define ZERO_COUNT 1044480

// ---------- transpose x: [B][N] -> [N][B] ----------
__global__ void k_transpose_in(const float* __restrict__ x) {
    __shared__ float tile[32][33];
    int i0 = blockIdx.x * 32;
    int tx = threadIdx.x, ty = threadIdx.y;
    tile[ty][tx] = x[(size_t)ty * NTOT + i0 + tx];
    __syncthreads();
    g_xT[(size_t)(i0 + ty) * BATCH + tx] = tile[tx][ty];
}

__global__ void k_zero_t() {
    int i = blockIdx.x * blockDim.x + threadIdx.x;
    if (i < ZERO_COUNT) g_t[i] = 0.f;
}

// ---------- phase 1 per-level worker ----------
// t[block, r, n] = sum_{s in block} U[s, r] * x[s, n]
template<int R, bool ATOMIC, int SPLIT>
__device__ __forceinline__ void p1_level(const float* __restrict__ u, const float* __restrict__ xs,
                                         int slice, int w, int lane, int toff, int bszLog) {
    constexpr int NTILE = (R + 7) / 8;
    constexpr int RANGE = 256 / SPLIT;
    int sub, tile;
    if (SPLIT == 1) {
        if (w >= NTILE) return;
        sub = 0; tile = w;
    } else {
        sub = w / NTILE; tile = w - sub * NTILE;
        if (sub >= SPLIT) return;
    }
    int bsz = 1 << bszLog;
    int step = bsz < RANGE ? bsz : RANGE;
    int r0 = tile * 8;
    bool isTail = ((R % 8) != 0) && (tile == NTILE - 1);

    for (int off = 0; off < RANGE; off += step) {
        int locals = sub * RANGE + off;
        int sbeg = slice * 256 + locals;
        int block = sbeg >> bszLog;
        ull a0 = 0, a1 = 0, a2 = 0, a3 = 0;
        const char* uptr = (const char*)(u + (size_t)sbeg * R + r0);
        const float* xp = xs + locals * 32 + lane;
        if (!isTail) {
            #pragma unroll 4
            for (int sl = 0; sl < step; sl++) {
                float xv = xp[sl * 32];
                ull x2 = f2pack(xv, xv);
                ulonglong2 v0 = __ldg((const ulonglong2*)uptr);
                ulonglong2 v1 = __ldg((const ulonglong2*)(uptr + 16));
                a0 = ffma2(v0.x, x2, a0);
                a1 = ffma2(v0.y, x2, a1);
                a2 = ffma2(v1.x, x2, a2);
                a3 = ffma2(v1.y, x2, a3);
                uptr += R * 4;
            }
        } else {
            #pragma unroll 4
            for (int sl = 0; sl < step; sl++) {
                float xv = xp[sl * 32];
                ull x2 = f2pack(xv, xv);
                ulonglong2 v0 = __ldg((const ulonglong2*)uptr);
                a0 = ffma2(v0.x, x2, a0);
                a1 = ffma2(v0.y, x2, a1);
                uptr += R * 4;
            }
        }
        float* td = g_t + toff + ((size_t)block * R + r0) * 32 + lane;
        float lo, hi;
        f2unpack(lo, hi, a0);
        if (ATOMIC) { atomicAdd(td, lo);       atomicAdd(td + 32, hi); }
        else        { td[0] = lo;              td[32] = hi; }
        f2unpack(lo, hi, a1);
        if (ATOMIC) { atomicAdd(td + 64, lo);  atomicAdd(td + 96, hi); }
        else        { td[64] = lo;             td[96] = hi; }
        if (!isTail) {
            f2unpack(lo, hi, a2);
            if (ATOMIC) { atomicAdd(td + 128, lo); atomicAdd(td + 160, hi); }
            else        { td[128] = lo;            td[160] = hi; }
            f2unpack(lo, hi, a3);
            if (ATOMIC) { atomicAdd(td + 192, lo); atomicAdd(td + 224, hi); }
            else        { td[192] = lo;            td[224] = hi; }
        }
    }
}

__global__ void __launch_bounds__(256) k_p1(P p) {
    __shared__ float xs[8192];    // 256 s x 32 n
    int tid = threadIdx.x, slice = blockIdx.x;
    const float4* src = (const float4*)(g_xT + (size_t)slice * 8192);
    float4* dst = (float4*)xs;
    #pragma unroll
    for (int i = 0; i < 8; i++) dst[tid + i * 256] = src[tid + i * 256];
    __syncthreads();
    int w = tid >> 5, lane = tid & 31;

    static const int toffA[8] = {TOFF0, TOFF1, TOFF2, TOFF3, TOFF4, TOFF5, TOFF6, TOFF7};
    #pragma unroll 1
    for (int l = 0; l < 8; l++)
        p1_level<64, true, 1>(p.u[l], xs, slice, w, lane, toffA[l], 16 - l);
    p1_level<64, false, 1>(p.u[8],  xs, slice, w, lane, TOFF8,  8);
    p1_level<52, false, 1>(p.u[9],  xs, slice, w, lane, TOFF9,  7);
    p1_level<32, false, 2>(p.u[10], xs, slice, w, lane, TOFF10, 6);
    p1_level<20, false, 2>(p.u[11], xs, slice, w, lane, TOFF11, 5);
}

// ---------- epilogue per-level worker ----------
// ts[sl][lane] += s2 * sum_r U[s0+sl, r] * t_sib[r, lane]
template<int R>
__device__ __forceinline__ void epi_level(const float* __restrict__ u, const float* __restrict__ tb,
                                          int s0, int lane, float s2, float* __restrict__ ts) {
    ull tp[R / 2];
    #pragma unroll
    for (int j = 0; j < R / 2; j++)
        tp[j] = f2pack(__ldg(tb + (2 * j) * 32 + lane), __ldg(tb + (2 * j + 1) * 32 + lane));
    const char* uptr = (const char*)(u + (size_t)s0 * R);
    #pragma unroll 2
    for (int sl = 0; sl < 32; sl++) {
        ull a0 = 0, a1 = 0, a2 = 0, a3 = 0;
        #pragma unroll
        for (int j = 0; j < R / 4; j++) {
            ulonglong2 v = __ldg((const ulonglong2*)(uptr + j * 16));
            if (j & 1) { a2 = ffma2(v.x, tp[2 * j], a2); a3 = ffma2(v.y, tp[2 * j + 1], a3); }
            else       { a0 = ffma2(v.x, tp[2 * j], a0); a1 = ffma2(v.y, tp[2 * j + 1], a1); }
        }
        float l0, h0, l1, h1, l2, h2, l3, h3;
        f2unpack(l0, h0, a0); f2unpack(l1, h1, a1);
        f2unpack(l2, h2, a2); f2unpack(l3, h3, a3);
        float v = ((l0 + h0) + (l1 + h1)) + ((l2 + h2) + (l3 + h3));
        ts[sl * 33 + lane] += s2 * v;
        uptr += (size_t)R * 4;
    }
}

// ---------- fused epilogue: leaf GEMM + 12 level applies + transpose-out ----------
__global__ void __launch_bounds__(128) k_epi(P p, const float* __restrict__ lb,
                                             const float* __restrict__ sc,
                                             float* __restrict__ out) {
    __shared__ float tile[4][33 * 32];
    int tid = threadIdx.x, w = tid >> 5, lane = tid & 31;
    int s0 = (blockIdx.x * 4 + w) * 32;
    float* ts = tile[w];

    // --- leaf: ts[t][n] = sum_s lb[k,t,s] * x[s0+s, n] ---
    ull xp[16];
    {
        const float* xb = g_xT + (size_t)s0 * 32 + lane;
        #pragma unroll
        for (int j = 0; j < 16; j++)
            xp[j] = f2pack(xb[(2 * j) * 32], xb[(2 * j + 1) * 32]);
    }
    const char* lptr = (const char*)(lb + (size_t)s0 * 32);  // k*1024 == s0*32
    #pragma unroll 2
    for (int t = 0; t < 32; t++) {
        ull a0 = 0, a1 = 0, a2 = 0, a3 = 0;
        #pragma unroll
        for (int j = 0; j < 8; j++) {
            ulonglong2 v = __ldg((const ulonglong2*)(lptr + j * 16));
            if (j & 1) { a2 = ffma2(v.x, xp[2 * j], a2); a3 = ffma2(v.y, xp[2 * j + 1], a3); }
            else       { a0 = ffma2(v.x, xp[2 * j], a0); a1 = ffma2(v.y, xp[2 * j + 1], a1); }
        }
        float l0, h0, l1, h1, l2, h2, l3, h3;
        f2unpack(l0, h0, a0); f2unpack(l1, h1, a1);
        f2unpack(l2, h2, a2); f2unpack(l3, h3, a3);
        ts[t * 33 + lane] = ((l0 + h0) + (l1 + h1)) + ((l2 + h2) + (l3 + h3));
        lptr += 128;
    }

    float scv = __ldg(sc);
    float s2 = scv * scv;

    static const int toffA[9] = {TOFF0, TOFF1, TOFF2, TOFF3, TOFF4, TOFF5, TOFF6, TOFF7, TOFF8};
    #pragma unroll 1
    for (int l = 0; l < 9; l++) {
        int bszLog = 16 - l;
        int sib = (s0 >> bszLog) ^ 1;
        epi_level<64>(p.u[l], g_t + toffA[l] + (size_t)sib * (64 * 32), s0, lane, s2, ts);
    }
    { int sib = (s0 >> 7) ^ 1; epi_level<52>(p.u[9],  g_t + TOFF9  + (size_t)sib * (52 * 32), s0, lane, s2, ts); }
    { int sib = (s0 >> 6) ^ 1; epi_level<32>(p.u[10], g_t + TOFF10 + (size_t)sib * (32 * 32), s0, lane, s2, ts); }
    { int sib = (s0 >> 5) ^ 1; epi_level<20>(p.u[11], g_t + TOFF11 + (size_t)sib * (20 * 32), s0, lane, s2, ts); }

    __syncwarp();
    // transpose-out: out[n][s0+lane] = ts[lane][n]
    #pragma unroll
    for (int n = 0; n < 32; n++)
        out[(size_t)n * NTOT + s0 + lane] = ts[lane * 33 + n];
}

// ---------- driver ----------
extern "C" void kernel_launch(void* const* d_in, const int* in_sizes, int n_in,
                              void* d_out, int out_size) {
    (void)in_sizes; (void)n_in; (void)out_size;
    const float* x  = (const float*)d_in[0];
    const float* lb = (const float*)d_in[1];
    const float* sc = (const float*)d_in[2];
    P p;
    for (int l = 0; l < 12; l++) p.u[l] = (const float*)d_in[3 + l];
    float* out = (float*)d_out;

    k_transpose_in<<<4096, dim3(32, 32)>>>(x);
    k_zero_t<<<(ZERO_COUNT + 1023) / 1024, 1024>>>();
    k_p1<<<512, 256>>>(p);
    k_epi<<<1024, 128>>>(p, lb, sc, out);
}

// round 3
// speedup vs baseline: 2.9469x; 2.3428x over previous
#include <cuda_runtime.h>

#define NTOT 131072

typedef unsigned long long ull;

// ---------- f32x2 packed-math helpers (sm_103a) ----------
__device__ __forceinline__ ull f2pack(float lo, float hi) {
    ull r; asm("mov.b64 %0, {%1, %2};" : "=l"(r) : "f"(lo), "f"(hi)); return r;
}
__device__ __forceinline__ void f2unpack(float& lo, float& hi, ull v) {
    asm("mov.b64 {%0, %1}, %2;" : "=f"(lo), "=f"(hi) : "l"(v));
}
__device__ __forceinline__ ull ffma2(ull a, ull b, ull c) {
    ull d; asm("fma.rn.f32x2 %0, %1, %2, %3;" : "=l"(d) : "l"(a), "l"(b), "l"(c)); return d;
}
__device__ __forceinline__ ull fadd2(ull a, ull b) {
    ull d; asm("add.rn.f32x2 %0, %1, %2;" : "=l"(d) : "l"(a), "l"(b)); return d;
}

// ---------- scratch (device globals; 16B-aligned via float4) ----------
__device__ float4 g_xT4[NTOT * 32 / 4];
__device__ float4 g_t4[8515584 / 4];
#define g_xT ((float*)g_xT4)
#define g_t  ((float*)g_t4)

// t-buffer offsets per level (in floats); layout per level: [block][rpair j][lane n] as float2
#define TOFF0 0
#define TOFF1 4096
#define TOFF2 12288
#define TOFF3 28672
#define TOFF4 61440
#define TOFF5 126976
#define TOFF6 258048
#define TOFF7 520192
#define TOFF8 1044480
#define TOFF9 2093056
#define TOFF10 3796992
#define TOFF11 5894144
#define ZERO_COUNT 2093056   // levels 0-8 are atomic

__device__ __constant__ int c_toffA[9] = {TOFF0, TOFF1, TOFF2, TOFF3, TOFF4,
                                          TOFF5, TOFF6, TOFF7, TOFF8};

struct P { const float* u[12]; };

// ---------- transpose x: [B][N] -> [N][B] ----------
__global__ void k_transpose_in(const float* __restrict__ x) {
    __shared__ float tile[32][33];
    int i0 = blockIdx.x * 32;
    int tx = threadIdx.x, ty = threadIdx.y;
    tile[ty][tx] = x[(size_t)ty * NTOT + i0 + tx];
    __syncthreads();
    g_xT[(size_t)(i0 + ty) * 32 + tx] = tile[tx][ty];
}

__global__ void k_zero_t() {
    int i = blockIdx.x * blockDim.x + threadIdx.x;
    if (i < ZERO_COUNT / 4) g_t4[i] = make_float4(0.f, 0.f, 0.f, 0.f);
}

// ---------- cooperative stage: gmem -> smem (coalesced float4) ----------
__device__ __forceinline__ void stage(float* __restrict__ dst, const float* __restrict__ src,
                                      int nf4, int tid) {
    const float4* s4 = (const float4*)src;
    float4* d4 = (float4*)dst;
    #pragma unroll 4
    for (int i = tid; i < nf4; i += 256) d4[i] = s4[i];
}

// ---------- phase 1 tile worker ----------
// t[block, r0..r0+RW) += sum_s U[s, r] * x[s, n];  U staged in smem (us), x in smem (xs)
template<int R, int RW, bool ATOMIC>
__device__ __forceinline__ void p1_tile(const float* __restrict__ us, const float* __restrict__ xs,
                                        int slice, int sbeg, int scount, int bszLog,
                                        int r0, int toff, int lane) {
    int bsz = 1 << bszLog;
    int step = bsz < scount ? bsz : scount;
    for (int off = 0; off < scount; off += step) {
        int sl0 = sbeg + off;
        ull a0 = 0, a1 = 0, a2 = 0, a3 = 0, a4 = 0, a5 = 0, a6 = 0, a7 = 0;
        const float* up = us + sl0 * R + r0;
        const float* xp = xs + sl0 * 32 + lane;
        #pragma unroll 4
        for (int s = 0; s < step; s++) {
            float xv = xp[s * 32];
            ull x2 = f2pack(xv, xv);
            ulonglong2 v0 = *(const ulonglong2*)up;
            a0 = ffma2(v0.x, x2, a0); a1 = ffma2(v0.y, x2, a1);
            if (RW >= 8) {
                ulonglong2 v1 = *(const ulonglong2*)(up + 4);
                a2 = ffma2(v1.x, x2, a2); a3 = ffma2(v1.y, x2, a3);
            }
            if (RW >= 16) {
                ulonglong2 v2 = *(const ulonglong2*)(up + 8);
                a4 = ffma2(v2.x, x2, a4); a5 = ffma2(v2.y, x2, a5);
                ulonglong2 v3 = *(const ulonglong2*)(up + 12);
                a6 = ffma2(v3.x, x2, a6); a7 = ffma2(v3.y, x2, a7);
            }
            up += R;
        }
        int block = (slice * 256 + sl0) >> bszLog;
        float* td = g_t + toff + (((size_t)block * (R / 2) + (r0 >> 1)) * 32 + lane) * 2;
        ull av[8] = {a0, a1, a2, a3, a4, a5, a6, a7};
        #pragma unroll
        for (int k = 0; k < RW / 2; k++) {
            float lo, hi; f2unpack(lo, hi, av[k]);
            float* p = td + k * 64;
            if (ATOMIC) { atomicAdd(p, lo); atomicAdd(p + 1, hi); }
            else        { *(float2*)p = make_float2(lo, hi); }
        }
    }
}

// ---------- phase 1 kernel: all 12 levels, per-CTA 256-s slice ----------
__global__ void __launch_bounds__(256, 2) k_p1(P p) {
    extern __shared__ float sm[];          // xs[8192] + us[16384]
    float* xs = sm;
    float* us = sm + 8192;
    int tid = threadIdx.x, slice = blockIdx.x;
    int w = tid >> 5, lane = tid & 31;

    stage(xs, g_xT + (size_t)slice * 8192, 2048, tid);

    // levels 0-8: R=64, atomic; 4 r-tiles of 16 x 2 s-halves
    #pragma unroll 1
    for (int l = 0; l < 9; l++) {
        __syncthreads();
        stage(us, p.u[l] + (size_t)slice * 16384, 4096, tid);
        __syncthreads();
        p1_tile<64, 16, true>(us, xs, slice, (w >> 2) * 128, 128, 16 - l,
                              (w & 3) * 16, c_toffA[l], lane);
    }
    // level 9: R=52, bsz=128
    __syncthreads();
    stage(us, p.u[9] + (size_t)slice * 13312, 3328, tid);
    __syncthreads();
    {
        int tile = w & 3, half = w >> 2;
        if (tile < 3) p1_tile<52, 16, false>(us, xs, slice, half * 128, 128, 7, tile * 16, TOFF9, lane);
        else          p1_tile<52, 4,  false>(us, xs, slice, half * 128, 128, 7, 48,       TOFF9, lane);
    }
    // level 10: R=32, bsz=64
    __syncthreads();
    stage(us, p.u[10] + (size_t)slice * 8192, 2048, tid);
    __syncthreads();
    {
        int tile = w & 1, q = w >> 1;
        p1_tile<32, 16, false>(us, xs, slice, q * 64, 64, 6, tile * 16, TOFF10, lane);
    }
    // level 11: R=20, bsz=32
    __syncthreads();
    stage(us, p.u[11] + (size_t)slice * 5120, 1280, tid);
    __syncthreads();
    {
        int tile = w & 1, q = w >> 1;
        if (tile == 0) p1_tile<20, 16, false>(us, xs, slice, q * 64, 64, 5, 0,  TOFF11, lane);
        else           p1_tile<20, 4,  false>(us, xs, slice, q * 64, 64, 5, 16, TOFF11, lane);
    }
}

// ---------- epilogue level worker ----------
// ys[sl][lane] += sum_r U[s0+sl, r] * (s2 * t_sib[r, lane]);  U in smem
template<int R>
__device__ __forceinline__ void epi_level(const float* __restrict__ us, const float2* __restrict__ tb,
                                          int s0l, int lane, float s2, float* __restrict__ ys) {
    ull tp[R / 2];
    #pragma unroll
    for (int j = 0; j < R / 2; j++) {
        float2 t = __ldg(tb + j * 32 + lane);
        tp[j] = f2pack(s2 * t.x, s2 * t.y);
    }
    const float* up = us + s0l * R;
    #pragma unroll 2
    for (int sl = 0; sl < 32; sl++) {
        ull a0 = 0, a1 = 0, a2 = 0, a3 = 0;
        #pragma unroll
        for (int j = 0; j < R / 4; j++) {
            ulonglong2 v = *(const ulonglong2*)(up + j * 4);
            if (j & 1) { a2 = ffma2(v.x, tp[2 * j], a2); a3 = ffma2(v.y, tp[2 * j + 1], a3); }
            else       { a0 = ffma2(v.x, tp[2 * j], a0); a1 = ffma2(v.y, tp[2 * j + 1], a1); }
        }
        ull s01 = fadd2(a0, a1), s23 = fadd2(a2, a3), v2 = fadd2(s01, s23);
        float lo, hi; f2unpack(lo, hi, v2);
        ys[sl * 33 + lane] += lo + hi;
        up += R;
    }
}

// ---------- leaf worker: ys[t][lane] = sum_s lb[k,t,s] * x[k*32+s, lane] ----------
__device__ __forceinline__ void leaf_w(const float* __restrict__ us_lb, int w, int lane,
                                       int s0g, float* __restrict__ ys) {
    ull xp[16];
    const float* xb = g_xT + (size_t)s0g * 32 + lane;
    #pragma unroll
    for (int j = 0; j < 16; j++)
        xp[j] = f2pack(__ldg(xb + (2 * j) * 32), __ldg(xb + (2 * j + 1) * 32));
    const float* lp = us_lb + w * 1024;
    #pragma unroll 2
    for (int t = 0; t < 32; t++) {
        ull a0 = 0, a1 = 0, a2 = 0, a3 = 0;
        #pragma unroll
        for (int j = 0; j < 8; j++) {
            ulonglong2 v = *(const ulonglong2*)(lp + t * 32 + j * 4);
            if (j & 1) { a2 = ffma2(v.x, xp[2 * j], a2); a3 = ffma2(v.y, xp[2 * j + 1], a3); }
            else       { a0 = ffma2(v.x, xp[2 * j], a0); a1 = ffma2(v.y, xp[2 * j + 1], a1); }
        }
        ull s01 = fadd2(a0, a1), s23 = fadd2(a2, a3), v2 = fadd2(s01, s23);
        float lo, hi; f2unpack(lo, hi, v2);
        ys[t * 33 + lane] = lo + hi;
    }
}

// ---------- fused epilogue: leaf + 12 level applies + transpose-out ----------
__global__ void __launch_bounds__(256, 2) k_epi(P p, const float* __restrict__ lb,
                                                const float* __restrict__ sc,
                                                float* __restrict__ out) {
    extern __shared__ float sm[];          // us[16384] + ys[8 * 33*32]
    float* us = sm;
    float* ys_all = sm + 16384;
    int tid = threadIdx.x, slice = blockIdx.x;
    int w = tid >> 5, lane = tid & 31;
    int s0l = w * 32, s0g = slice * 256 + s0l;
    float* ys = ys_all + w * (33 * 32);

    // leaf
    stage(us, lb + (size_t)slice * 8192, 2048, tid);
    __syncthreads();
    leaf_w(us, w, lane, s0g, ys);

    float scv = __ldg(sc);
    float s2 = scv * scv;

    // levels 0-8: R=64
    #pragma unroll 1
    for (int l = 0; l < 9; l++) {
        __syncthreads();
        stage(us, p.u[l] + (size_t)slice * 16384, 4096, tid);
        __syncthreads();
        int sib = (s0g >> (16 - l)) ^ 1;
        epi_level<64>(us, (const float2*)(g_t + c_toffA[l]) + (size_t)sib * 1024, s0l, lane, s2, ys);
    }
    // level 9: R=52
    __syncthreads();
    stage(us, p.u[9] + (size_t)slice * 13312, 3328, tid);
    __syncthreads();
    { int sib = (s0g >> 7) ^ 1;
      epi_level<52>(us, (const float2*)(g_t + TOFF9) + (size_t)sib * 832, s0l, lane, s2, ys); }
    // level 10: R=32
    __syncthreads();
    stage(us, p.u[10] + (size_t)slice * 8192, 2048, tid);
    __syncthreads();
    { int sib = (s0g >> 6) ^ 1;
      epi_level<32>(us, (const float2*)(g_t + TOFF10) + (size_t)sib * 512, s0l, lane, s2, ys); }
    // level 11: R=20
    __syncthreads();
    stage(us, p.u[11] + (size_t)slice * 5120, 1280, tid);
    __syncthreads();
    { int sib = (s0g >> 5) ^ 1;
      epi_level<20>(us, (const float2*)(g_t + TOFF11) + (size_t)sib * 320, s0l, lane, s2, ys); }

    __syncwarp();
    // transpose-out: out[n][s0g+lane] = ys[lane][n]
    #pragma unroll
    for (int n = 0; n < 32; n++)
        out[(size_t)n * NTOT + s0g + lane] = ys[lane * 33 + n];
}

// ---------- driver ----------
extern "C" void kernel_launch(void* const* d_in, const int* in_sizes, int n_in,
                              void* d_out, int out_size) {
    (void)in_sizes; (void)n_in; (void)out_size;
    const float* x  = (const float*)d_in[0];
    const float* lb = (const float*)d_in[1];
    const float* sc = (const float*)d_in[2];
    P p;
    for (int l = 0; l < 12; l++) p.u[l] = (const float*)d_in[3 + l];
    float* out = (float*)d_out;

    static const int SMEM_P1  = (8192 + 16384) * 4;            // 98304
    static const int SMEM_EPI = (16384 + 8 * 33 * 32) * 4;     // 99328
    cudaFuncSetAttribute(k_p1,  cudaFuncAttributeMaxDynamicSharedMemorySize, SMEM_P1);
    cudaFuncSetAttribute(k_epi, cudaFuncAttributeMaxDynamicSharedMemorySize, SMEM_EPI);

    k_transpose_in<<<4096, dim3(32, 32)>>>(x);
    k_zero_t<<<(ZERO_COUNT / 4 + 255) / 256, 256>>>();
    k_p1<<<512, 256, SMEM_P1>>>(p);
    k_epi<<<512, 256, SMEM_EPI>>>(p, lb, sc, out);
}

// round 4
// speedup vs baseline: 2.9610x; 1.0048x over previous
#include <cuda_runtime.h>

#define NTOT 131072

typedef unsigned long long ull;

// ---------- f32x2 packed-math helpers (sm_103a) ----------
__device__ __forceinline__ ull f2pack(float lo, float hi) {
    ull r; asm("mov.b64 %0, {%1, %2};" : "=l"(r) : "f"(lo), "f"(hi)); return r;
}
__device__ __forceinline__ void f2unpack(float& lo, float& hi, ull v) {
    asm("mov.b64 {%0, %1}, %2;" : "=f"(lo), "=f"(hi) : "l"(v));
}
__device__ __forceinline__ ull ffma2(ull a, ull b, ull c) {
    ull d; asm("fma.rn.f32x2 %0, %1, %2, %3;" : "=l"(d) : "l"(a), "l"(b), "l"(c)); return d;
}
__device__ __forceinline__ ull fadd2(ull a, ull b) {
    ull d; asm("add.rn.f32x2 %0, %1, %2;" : "=l"(d) : "l"(a), "l"(b)); return d;
}

// ---------- scratch (device globals; 16B-aligned via float4) ----------
__device__ float4 g_xT4[NTOT * 32 / 4];
__device__ float4 g_t4[8515584 / 4];
#define g_xT ((float*)g_xT4)
#define g_t  ((float*)g_t4)

// t-buffer offsets per level (in floats); layout per level: [block][rpair j][lane n] as float2
#define TOFF0 0
#define TOFF1 4096
#define TOFF2 12288
#define TOFF3 28672
#define TOFF4 61440
#define TOFF5 126976
#define TOFF6 258048
#define TOFF7 520192
#define TOFF8 1044480
#define TOFF9 2093056
#define TOFF10 3796992
#define TOFF11 5894144
#define ZERO_COUNT 2093056   // levels 0-8 are atomic

__device__ __constant__ int c_toffA[9] = {TOFF0, TOFF1, TOFF2, TOFF3, TOFF4,
                                          TOFF5, TOFF6, TOFF7, TOFF8};

struct P { const float* u[12]; };

// ---------- transpose x: [B][N] -> [N][B] ----------
__global__ void k_transpose_in(const float* __restrict__ x) {
    __shared__ float tile[32][33];
    int i0 = blockIdx.x * 32;
    int tx = threadIdx.x, ty = threadIdx.y;
    tile[ty][tx] = x[(size_t)ty * NTOT + i0 + tx];
    __syncthreads();
    g_xT[(size_t)(i0 + ty) * 32 + tx] = tile[tx][ty];
}

__global__ void k_zero_t() {
    int i = blockIdx.x * blockDim.x + threadIdx.x;
    if (i < ZERO_COUNT / 4) g_t4[i] = make_float4(0.f, 0.f, 0.f, 0.f);
}

// ---------- cooperative stage: gmem -> smem (coalesced float4) ----------
__device__ __forceinline__ void stage(float* __restrict__ dst, const float* __restrict__ src,
                                      int nf4, int tid) {
    const float4* s4 = (const float4*)src;
    float4* d4 = (float4*)dst;
    #pragma unroll 4
    for (int i = tid; i < nf4; i += 256) d4[i] = s4[i];
}

// ---------- phase 1 tile worker ----------
// t[block, r0..r0+RW) += sum_s U[s, r] * x[s, n];  U staged in smem (us), x in smem (xs)
template<int R, int RW, bool ATOMIC>
__device__ __forceinline__ void p1_tile(const float* __restrict__ us, const float* __restrict__ xs,
                                        int slice, int sbeg, int scount, int bszLog,
                                        int r0, int toff, int lane) {
    int bsz = 1 << bszLog;
    int step = bsz < scount ? bsz : scount;
    for (int off = 0; off < scount; off += step) {
        int sl0 = sbeg + off;
        ull a0 = 0, a1 = 0, a2 = 0, a3 = 0, a4 = 0, a5 = 0, a6 = 0, a7 = 0;
        const float* up = us + sl0 * R + r0;
        const float* xp = xs + sl0 * 32 + lane;
        #pragma unroll 4
        for (int s = 0; s < step; s++) {
            float xv = xp[s * 32];
            ull x2 = f2pack(xv, xv);
            ulonglong2 v0 = *(const ulonglong2*)up;
            a0 = ffma2(v0.x, x2, a0); a1 = ffma2(v0.y, x2, a1);
            if (RW >= 8) {
                ulonglong2 v1 = *(const ulonglong2*)(up + 4);
                a2 = ffma2(v1.x, x2, a2); a3 = ffma2(v1.y, x2, a3);
            }
            if (RW >= 16) {
                ulonglong2 v2 = *(const ulonglong2*)(up + 8);
                a4 = ffma2(v2.x, x2, a4); a5 = ffma2(v2.y, x2, a5);
                ulonglong2 v3 = *(const ulonglong2*)(up + 12);
                a6 = ffma2(v3.x, x2, a6); a7 = ffma2(v3.y, x2, a7);
            }
            up += R;
        }
        int block = (slice * 256 + sl0) >> bszLog;
        float* td = g_t + toff + (((size_t)block * (R / 2) + (r0 >> 1)) * 32 + lane) * 2;
        ull av[8] = {a0, a1, a2, a3, a4, a5, a6, a7};
        #pragma unroll
        for (int k = 0; k < RW / 2; k++) {
            float lo, hi; f2unpack(lo, hi, av[k]);
            float* p = td + k * 64;
            if (ATOMIC) { atomicAdd(p, lo); atomicAdd(p + 1, hi); }
            else        { *(float2*)p = make_float2(lo, hi); }
        }
    }
}

// ---------- phase 1 kernel: all 12 levels, per-CTA 256-s slice ----------
__global__ void __launch_bounds__(256, 2) k_p1(P p) {
    extern __shared__ float sm[];          // xs[8192] + us[16384]
    float* xs = sm;
    float* us = sm + 8192;
    int tid = threadIdx.x, slice = blockIdx.x;
    int w = tid >> 5, lane = tid & 31;

    stage(xs, g_xT + (size_t)slice * 8192, 2048, tid);

    // levels 0-8: R=64, atomic; 4 r-tiles of 16 x 2 s-halves
    #pragma unroll 1
    for (int l = 0; l < 9; l++) {
        __syncthreads();
        stage(us, p.u[l] + (size_t)slice * 16384, 4096, tid);
        __syncthreads();
        p1_tile<64, 16, true>(us, xs, slice, (w >> 2) * 128, 128, 16 - l,
                              (w & 3) * 16, c_toffA[l], lane);
    }
    // level 9: R=52, bsz=128
    __syncthreads();
    stage(us, p.u[9] + (size_t)slice * 13312, 3328, tid);
    __syncthreads();
    {
        int tile = w & 3, half = w >> 2;
        if (tile < 3) p1_tile<52, 16, false>(us, xs, slice, half * 128, 128, 7, tile * 16, TOFF9, lane);
        else          p1_tile<52, 4,  false>(us, xs, slice, half * 128, 128, 7, 48,       TOFF9, lane);
    }
    // level 10: R=32, bsz=64
    __syncthreads();
    stage(us, p.u[10] + (size_t)slice * 8192, 2048, tid);
    __syncthreads();
    {
        int tile = w & 1, q = w >> 1;
        p1_tile<32, 16, false>(us, xs, slice, q * 64, 64, 6, tile * 16, TOFF10, lane);
    }
    // level 11: R=20, bsz=32
    __syncthreads();
    stage(us, p.u[11] + (size_t)slice * 5120, 1280, tid);
    __syncthreads();
    {
        int tile = w & 1, q = w >> 1;
        if (tile == 0) p1_tile<20, 16, false>(us, xs, slice, q * 64, 64, 5, 0,  TOFF11, lane);
        else           p1_tile<20, 4,  false>(us, xs, slice, q * 64, 64, 5, 16, TOFF11, lane);
    }
}

// ---------- epilogue level worker ----------
// ys[sl][lane] += sum_r U[s0+sl, r] * (s2 * t_sib[r, lane]);  U in smem
template<int R>
__device__ __forceinline__ void epi_level(const float* __restrict__ us, const float2* __restrict__ tb,
                                          int s0l, int lane, float s2, float* __restrict__ ys) {
    ull tp[R / 2];
    #pragma unroll
    for (int j = 0; j < R / 2; j++) {
        float2 t = __ldg(tb + j * 32 + lane);
        tp[j] = f2pack(s2 * t.x, s2 * t.y);
    }
    const float* up = us + s0l * R;
    #pragma unroll 2
    for (int sl = 0; sl < 32; sl++) {
        ull a0 = 0, a1 = 0, a2 = 0, a3 = 0;
        #pragma unroll
        for (int j = 0; j < R / 4; j++) {
            ulonglong2 v = *(const ulonglong2*)(up + j * 4);
            if (j & 1) { a2 = ffma2(v.x, tp[2 * j], a2); a3 = ffma2(v.y, tp[2 * j + 1], a3); }
            else       { a0 = ffma2(v.x, tp[2 * j], a0); a1 = ffma2(v.y, tp[2 * j + 1], a1); }
        }
        ull s01 = fadd2(a0, a1), s23 = fadd2(a2, a3), v2 = fadd2(s01, s23);
        float lo, hi; f2unpack(lo, hi, v2);
        ys[sl * 33 + lane] += lo + hi;
        up += R;
    }
}

// ---------- leaf worker: ys[t][lane] = sum_s lb[k,t,s] * x[k*32+s, lane] ----------
__device__ __forceinline__ void leaf_w(const float* __restrict__ us_lb, int w, int lane,
                                       int s0g, float* __restrict__ ys) {
    ull xp[16];
    const float* xb = g_xT + (size_t)s0g * 32 + lane;
    #pragma unroll
    for (int j = 0; j < 16; j++)
        xp[j] = f2pack(__ldg(xb + (2 * j) * 32), __ldg(xb + (2 * j + 1) * 32));
    const float* lp = us_lb + w * 1024;
    #pragma unroll 2
    for (int t = 0; t < 32; t++) {
        ull a0 = 0, a1 = 0, a2 = 0, a3 = 0;
        #pragma unroll
        for (int j = 0; j < 8; j++) {
            ulonglong2 v = *(const ulonglong2*)(lp + t * 32 + j * 4);
            if (j & 1) { a2 = ffma2(v.x, xp[2 * j], a2); a3 = ffma2(v.y, xp[2 * j + 1], a3); }
            else       { a0 = ffma2(v.x, xp[2 * j], a0); a1 = ffma2(v.y, xp[2 * j + 1], a1); }
        }
        ull s01 = fadd2(a0, a1), s23 = fadd2(a2, a3), v2 = fadd2(s01, s23);
        float lo, hi; f2unpack(lo, hi, v2);
        ys[t * 33 + lane] = lo + hi;
    }
}

// ---------- fused epilogue: leaf + 12 level applies + transpose-out ----------
__global__ void __launch_bounds__(256, 2) k_epi(P p, const float* __restrict__ lb,
                                                const float* __restrict__ sc,
                                                float* __restrict__ out) {
    extern __shared__ float sm[];          // us[16384] + ys[8 * 33*32]
    float* us = sm;
    float* ys_all = sm + 16384;
    int tid = threadIdx.x, slice = blockIdx.x;
    int w = tid >> 5, lane = tid & 31;
    int s0l = w * 32, s0g = slice * 256 + s0l;
    float* ys = ys_all + w * (33 * 32);

    // leaf
    stage(us, lb + (size_t)slice * 8192, 2048, tid);
    __syncthreads();
    leaf_w(us, w, lane, s0g, ys);

    float scv = __ldg(sc);
    float s2 = scv * scv;

    // levels 0-8: R=64
    #pragma unroll 1
    for (int l = 0; l < 9; l++) {
        __syncthreads();
        stage(us, p.u[l] + (size_t)slice * 16384, 4096, tid);
        __syncthreads();
        int sib = (s0g >> (16 - l)) ^ 1;
        epi_level<64>(us, (const float2*)(g_t + c_toffA[l]) + (size_t)sib * 1024, s0l, lane, s2, ys);
    }
    // level 9: R=52
    __syncthreads();
    stage(us, p.u[9] + (size_t)slice * 13312, 3328, tid);
    __syncthreads();
    { int sib = (s0g >> 7) ^ 1;
      epi_level<52>(us, (const float2*)(g_t + TOFF9) + (size_t)sib * 832, s0l, lane, s2, ys); }
    // level 10: R=32
    __syncthreads();
    stage(us, p.u[10] + (size_t)slice * 8192, 2048, tid);
    __syncthreads();
    { int sib = (s0g >> 6) ^ 1;
      epi_level<32>(us, (const float2*)(g_t + TOFF10) + (size_t)sib * 512, s0l, lane, s2, ys); }
    // level 11: R=20
    __syncthreads();
    stage(us, p.u[11] + (size_t)slice * 5120, 1280, tid);
    __syncthreads();
    { int sib = (s0g >> 5) ^ 1;
      epi_level<20>(us, (const float2*)(g_t + TOFF11) + (size_t)sib * 320, s0l, lane, s2, ys); }

    __syncwarp();
    // transpose-out: out[n][s0g+lane] = ys[lane][n]
    #pragma unroll
    for (int n = 0; n < 32; n++)
        out[(size_t)n * NTOT + s0g + lane] = ys[lane * 33 + n];
}

// ---------- driver ----------
extern "C" void kernel_launch(void* const* d_in, const int* in_sizes, int n_in,
                              void* d_out, int out_size) {
    (void)in_sizes; (void)n_in; (void)out_size;
    const float* x  = (const float*)d_in[0];
    const float* lb = (const float*)d_in[1];
    const float* sc = (const float*)d_in[2];
    P p;
    for (int l = 0; l < 12; l++) p.u[l] = (const float*)d_in[3 + l];
    float* out = (float*)d_out;

    static const int SMEM_P1  = (8192 + 16384) * 4;            // 98304
    static const int SMEM_EPI = (16384 + 8 * 33 * 32) * 4;     // 99328
    cudaFuncSetAttribute(k_p1,  cudaFuncAttributeMaxDynamicSharedMemorySize, SMEM_P1);
    cudaFuncSetAttribute(k_epi, cudaFuncAttributeMaxDynamicSharedMemorySize, SMEM_EPI);

    k_transpose_in<<<4096, dim3(32, 32)>>>(x);
    k_zero_t<<<(ZERO_COUNT / 4 + 255) / 256, 256>>>();
    k_p1<<<512, 256, SMEM_P1>>>(p);
    k_epi<<<512, 256, SMEM_EPI>>>(p, lb, sc, out);
}